// round 14
// baseline (speedup 1.0000x reference)
#include <cuda_runtime.h>
#include <cuda_fp16.h>
#include <cstdint>

// ---------------------------------------------------------------------------
// Fused Conv2d(1->16,5x5,pad2) + BN(inference) + ReLU + MaxPool2x2
//   x [128,1,224,224] f32 -> out [128,16,112,112] f32
//
// R13: portable tensor-core path (tcgen05 is sm_103a-gated and this harness
// targets plain sm_103 -> use warp-level mma.sync HMMA instead).
//   Implicit GEMM: D[M=32 pos/warp, N=16 ch] = A[M, K=32 taps] x B[K,N]
//   - per-thread im2col row (25 taps, fp16, padded to 32) -> smem (80B stride)
//   - ldmatrix.m8n8.x4 -> A fragments ; weight B fragments in registers
//   - 8x mma.sync.m16n8k16.f32.f16.f16.f32 per warp-tile
//   - pool via 2x shfl.xor + fmax ; bias+relu after max (commutes).
// ---------------------------------------------------------------------------

__device__ __half g_wh[16 * 32];   // BN-folded weights fp16, K padded to 32
__device__ float  g_bias[16];      // BN-folded bias fp32

__global__ void fuse_params_kernel(const float* __restrict__ w,
                                   const float* __restrict__ b,
                                   const float* __restrict__ gamma,
                                   const float* __restrict__ beta,
                                   const float* __restrict__ mean,
                                   const float* __restrict__ var) {
    int c = threadIdx.x;
    if (c < 16) {
        float s = gamma[c] * rsqrtf(var[c] + 1e-5f);
        g_bias[c] = b[c] * s + beta[c] - mean[c] * s;
#pragma unroll
        for (int k = 0; k < 32; k++)
            g_wh[c * 32 + k] = __float2half(k < 25 ? w[c * 25 + k] * s : 0.0f);
    }
}

__device__ __forceinline__ uint32_t smem_u32(const void* p) {
    uint32_t a;
    asm("{ .reg .u64 t; cvta.to.shared.u64 t, %1; cvt.u32.u64 %0, t; }"
        : "=r"(a) : "l"(p));
    return a;
}
__device__ __forceinline__ void ldmatrix_x4(uint32_t& r0, uint32_t& r1,
                                            uint32_t& r2, uint32_t& r3,
                                            uint32_t addr) {
    asm volatile("ldmatrix.sync.aligned.m8n8.x4.shared.b16 {%0,%1,%2,%3}, [%4];"
                 : "=r"(r0), "=r"(r1), "=r"(r2), "=r"(r3) : "r"(addr));
}
__device__ __forceinline__ void mma16816(float& d0, float& d1, float& d2, float& d3,
                                         uint32_t a0, uint32_t a1, uint32_t a2, uint32_t a3,
                                         uint32_t b0, uint32_t b1) {
    asm volatile(
        "mma.sync.aligned.m16n8k16.row.col.f32.f16.f16.f32 "
        "{%0,%1,%2,%3}, {%4,%5,%6,%7}, {%8,%9}, {%0,%1,%2,%3};"
        : "+f"(d0), "+f"(d1), "+f"(d2), "+f"(d3)
        : "r"(a0), "r"(a1), "r"(a2), "r"(a3), "r"(b0), "r"(b1));
}

// ---------------------------------------------------------------------------
// Tiling: pooled 112x112 per image -> 56x7 tiles of (2 pooled rows x 16 pooled
// cols) = 32 pooled px = 128 conv positions. Warp w owns positions 32w..32w+31
// = pooled quads 8w..8w+7. Thread lane: q=lane>>2 (warp-local quad), s=lane&3
// (dy,dx in the 2x2 conv quad).
// ---------------------------------------------------------------------------
#define TILES_PER_CTA 8
#define IMG_TILES     392   // 56 * 7
#define ROW_HALVES    40    // 32 halves data + 8 pad -> 80B stride (conflict-free)

__global__ __launch_bounds__(128, 4)
void conv_hmma_kernel(const float* __restrict__ x, float* __restrict__ out) {
    __shared__ __align__(16) __half smA[128 * ROW_HALVES];  // 10240 B
    __shared__ float sbias[16];

    const int tid  = threadIdx.x;
    const int wid  = tid >> 5;
    const int lane = tid & 31;

    if (tid < 16) sbias[tid] = g_bias[tid];
    __syncthreads();

    // ---- B fragments (weights), built once: bfrag[nb][kc][2]
    // mma B layout (col): b0={B[k0][n],B[k0+1][n]}, b1={B[k0+8][n],B[k0+9][n]}
    // with n = nb*8 + lane/4, k0 = kc*16 + (lane%4)*2 ; B[k][n] = w[n][k].
    uint32_t bfrag[2][2][2];
    {
        int tg = lane >> 2, tig = lane & 3;
#pragma unroll
        for (int nb = 0; nb < 2; nb++) {
#pragma unroll
            for (int kc = 0; kc < 2; kc++) {
                int n  = nb * 8 + tg;
                int k0 = kc * 16 + tig * 2;
                __half2 h0 = __halves2half2(g_wh[n * 32 + k0],     g_wh[n * 32 + k0 + 1]);
                __half2 h1 = __halves2half2(g_wh[n * 32 + k0 + 8], g_wh[n * 32 + k0 + 9]);
                bfrag[nb][kc][0] = *reinterpret_cast<uint32_t*>(&h0);
                bfrag[nb][kc][1] = *reinterpret_cast<uint32_t*>(&h1);
            }
        }
    }

    uint4* rowp = reinterpret_cast<uint4*>(smA + (wid * 32 + lane) * ROW_HALVES);
    // ldmatrix base: lane L -> row (L%16) of warp block, +16B for L>=16
    const uint32_t lmbase = smem_u32(smA) +
        (uint32_t)(wid * 32 + (lane & 15)) * (ROW_HALVES * 2) + (lane >> 4) * 16;

    const int q = lane >> 2, s = lane & 3;
    const int dy = s >> 1, dx = s & 1;

#pragma unroll 1
    for (int it = 0; it < TILES_PER_CTA; it++) {
        int g  = blockIdx.x * TILES_PER_CTA + it;
        int b  = g / IMG_TILES;
        int wt = g - b * IMG_TILES;
        int ty = wt / 7, tx = wt - ty * 7;

        int pp = wid * 8 + q;                 // pooled px index in tile (0..31)
        int py = 2 * ty + (pp >> 4);
        int px = 16 * tx + (pp & 15);
        int r  = 2 * py + dy;                 // conv row 0..223
        int c  = 2 * px + dx;                 // conv col 0..223

        // ---- im2col row: 5x5 window (r-2..r+2, c-2..c+2), zero-padded.
        // 6-wide aligned super-window [e-2..e+3], e = c&~1, 3 LDG.64 per row.
        const float* xb = x + b * (224 * 224);
        int e = c & ~1;
        float v[5][6];
#pragma unroll
        for (int i = 0; i < 5; i++) {
            int rr = r - 2 + i;
            bool rok = ((unsigned)rr < 224u);
            const float* rowg = xb + rr * 224 + (e - 2);
#pragma unroll
            for (int j = 0; j < 3; j++) {
                bool ok = rok && ((unsigned)(e - 2 + 2 * j) < 224u);
                float2 p = ok ? __ldg(reinterpret_cast<const float2*>(rowg + 2 * j))
                              : make_float2(0.f, 0.f);
                v[i][2 * j] = p.x; v[i][2 * j + 1] = p.y;
            }
        }
        bool odd = (c & 1);
        float tp[25];
#pragma unroll
        for (int i = 0; i < 5; i++)
#pragma unroll
            for (int j = 0; j < 5; j++)
                tp[i * 5 + j] = odd ? v[i][j + 1] : v[i][j];

        uint32_t a16[16];
#pragma unroll
        for (int i = 0; i < 12; i++) {
            __half2 h = __floats2half2_rn(tp[2 * i], tp[2 * i + 1]);
            a16[i] = *reinterpret_cast<uint32_t*>(&h);
        }
        { __half2 h = __floats2half2_rn(tp[24], 0.f);
          a16[12] = *reinterpret_cast<uint32_t*>(&h); }
        a16[13] = 0; a16[14] = 0; a16[15] = 0;

        __syncwarp();   // prior iter's ldmatrix reads done before overwrite
        rowp[0] = make_uint4(a16[0],  a16[1],  a16[2],  a16[3]);
        rowp[1] = make_uint4(a16[4],  a16[5],  a16[6],  a16[7]);
        rowp[2] = make_uint4(a16[8],  a16[9],  a16[10], a16[11]);
        rowp[3] = make_uint4(a16[12], a16[13], a16[14], a16[15]);
        __syncwarp();

#pragma unroll
        for (int mb = 0; mb < 2; mb++) {
            uint32_t a0, a1, a2, a3, a4, a5, a6, a7;
            uint32_t base = lmbase + (uint32_t)(mb * 16) * (ROW_HALVES * 2);
            ldmatrix_x4(a0, a1, a2, a3, base);        // k 0..15
            ldmatrix_x4(a4, a5, a6, a7, base + 32);   // k 16..31

#pragma unroll
            for (int nb = 0; nb < 2; nb++) {
                float d0 = 0.f, d1 = 0.f, d2 = 0.f, d3 = 0.f;
                mma16816(d0, d1, d2, d3, a0, a1, a2, a3,
                         bfrag[nb][0][0], bfrag[nb][0][1]);
                mma16816(d0, d1, d2, d3, a4, a5, a6, a7,
                         bfrag[nb][1][0], bfrag[nb][1][1]);

                // ---- pool over quad rows (lane bits 2,3), bias, relu, store
#pragma unroll
                for (int h = 0; h < 4; h++) {
                    float vv = (h == 0) ? d0 : (h == 1) ? d1 : (h == 2) ? d2 : d3;
                    vv = fmaxf(vv, __shfl_xor_sync(0xFFFFFFFFu, vv, 4));
                    vv = fmaxf(vv, __shfl_xor_sync(0xFFFFFFFFu, vv, 8));
                    if ((lane & 12) == 0) {   // row%4 == 0 -> writer
                        int ch = nb * 8 + (lane & 3) * 2 + (h & 1);
                        int Q  = mb * 4 + ((h >> 1) << 1) + (lane >> 4); // quad in warp
                        int qpp = wid * 8 + Q;
                        int qpy = 2 * ty + (qpp >> 4);
                        int qpx = 16 * tx + (qpp & 15);
                        float o = fmaxf(vv + sbias[ch], 0.0f);
                        out[((b * 16 + ch) * 112 + qpy) * 112 + qpx] = o;
                    }
                }
            }
        }
    }
}

extern "C" void kernel_launch(void* const* d_in, const int* in_sizes, int n_in,
                              void* d_out, int out_size) {
    const float* x     = (const float*)d_in[0];
    const float* w     = (const float*)d_in[1];
    const float* bias  = (const float*)d_in[2];
    const float* gamma = (const float*)d_in[3];
    const float* beta  = (const float*)d_in[4];
    const float* mean  = (const float*)d_in[5];
    const float* var   = (const float*)d_in[6];
    float* out = (float*)d_out;

    fuse_params_kernel<<<1, 32>>>(w, bias, gamma, beta, mean, var);
    // 128 images * 392 tiles / 8 tiles per CTA = 6272 CTAs
    conv_hmma_kernel<<<6272, 128>>>(x, out);
}

// round 15
// speedup vs baseline: 1.8224x; 1.8224x over previous
#include <cuda_runtime.h>
#include <cuda_fp16.h>
#include <cstdint>

// ---------------------------------------------------------------------------
// Fused Conv2d(1->16,5x5,pad2) + BN(inference) + ReLU + MaxPool2x2
//   x [128,1,224,224] f32 -> out [128,16,112,112] f32
//
// R14: HMMA implicit GEMM, wavefront-minimized.
//  - input tile staged cooperatively in smem (f32, halo included, zero-padded)
//  - A fragments built DIRECTLY in registers from the staged tile
//    (no STS / no ldmatrix); invalid taps read a guaranteed-zero smem cell
//  - M-row mapping row16 = dy*8 + dx*4 + q2 -> pooling = in-thread max + ONE
//    shfl.xor(16) per channel pair
//  - pooled results transposed through smem -> coalesced float4 stores
// Fragment layouts identical to R13 (validated, rel_err 2.3e-4).
// ---------------------------------------------------------------------------

__device__ __half g_wh[16 * 32];   // BN-folded weights fp16, K padded to 32
__device__ float  g_bias[16];      // BN-folded bias fp32

__global__ void fuse_params_kernel(const float* __restrict__ w,
                                   const float* __restrict__ b,
                                   const float* __restrict__ gamma,
                                   const float* __restrict__ beta,
                                   const float* __restrict__ mean,
                                   const float* __restrict__ var) {
    int c = threadIdx.x;
    if (c < 16) {
        float s = gamma[c] * rsqrtf(var[c] + 1e-5f);
        g_bias[c] = b[c] * s + beta[c] - mean[c] * s;
#pragma unroll
        for (int k = 0; k < 32; k++)
            g_wh[c * 32 + k] = __float2half(k < 25 ? w[c * 25 + k] * s : 0.0f);
    }
}

__device__ __forceinline__ void mma16816(float& d0, float& d1, float& d2, float& d3,
                                         uint32_t a0, uint32_t a1, uint32_t a2, uint32_t a3,
                                         uint32_t b0, uint32_t b1) {
    asm volatile(
        "mma.sync.aligned.m16n8k16.row.col.f32.f16.f16.f32 "
        "{%0,%1,%2,%3}, {%4,%5,%6,%7}, {%8,%9}, {%0,%1,%2,%3};"
        : "+f"(d0), "+f"(d1), "+f"(d2), "+f"(d3)
        : "r"(a0), "r"(a1), "r"(a2), "r"(a3), "r"(b0), "r"(b1));
}
__device__ __forceinline__ uint32_t h2(float lo, float hi) {
    __half2 h = __floats2half2_rn(lo, hi);
    return *reinterpret_cast<uint32_t*>(&h);
}

// ---------------------------------------------------------------------------
// CTA = 128 thr (4 warps). CTA-tile = 2 pooled rows x 16 pooled cols = 32
// pooled px = 128 conv positions. Warp w: pooled px pp = 8w..8w+7.
// Warp A-matrix (32 rows x 32 taps): M row (per 16-block mb) =
//   row16 = dy*8 + dx*4 + q2, quad Q = mb*4 + q2.
// Thread T (lane): i = T&3 (tap group), g = T>>2; holds rows g (dy=0) and
// g+8 (dy=1) with dx = g>>2, q2 = g&3.
// ---------------------------------------------------------------------------
#define TILES_PER_CTA 8
#define IMG_TILES     392   // 56 * 7
#define IN_STRIDE     40    // 36 valid cols + 4 zero cols (also the pad target)

__global__ __launch_bounds__(128, 6)
void conv_hmma_kernel(const float* __restrict__ x, float* __restrict__ out) {
    __shared__ float sm_in[8 * IN_STRIDE];   // staged input tile (halo incl.)
    __shared__ float sm_pool[16 * 36];       // pooled [ch]: 2x16 px, stride 36
    __shared__ float sbias[16];

    const int tid  = threadIdx.x;
    const int wid  = tid >> 5;
    const int lane = tid & 31;
    const int i4   = lane & 3;        // tap group
    const int g4   = lane >> 2;       // row group 0..7
    const int dxg  = g4 >> 2;         // dx of this thread's rows
    const int q2   = g4 & 3;

    if (tid < 16) sbias[tid] = g_bias[tid];

    // ---- B fragments (weights): validated R13 layout.
    uint32_t bfrag[2][2][2];
#pragma unroll
    for (int nb = 0; nb < 2; nb++)
#pragma unroll
        for (int kc = 0; kc < 2; kc++) {
            int n  = nb * 8 + g4;
            int k0 = kc * 16 + i4 * 2;
            bfrag[nb][kc][0] = h2(__half2float(g_wh[n * 32 + k0]),
                                  __half2float(g_wh[n * 32 + k0 + 1]));
            bfrag[nb][kc][1] = h2(__half2float(g_wh[n * 32 + k0 + 8]),
                                  __half2float(g_wh[n * 32 + k0 + 9]));
        }

    // ---- per-thread tap offsets (k = 2*i4 + 8j + h). Invalid taps -> col 39
    // of row 0/1, which is always zero (IN_STRIDE pad columns are zero-filled).
    int toff[4][2];
#pragma unroll
    for (int j = 0; j < 4; j++)
#pragma unroll
        for (int hh = 0; hh < 2; hh++) {
            int k = 2 * i4 + 8 * j + hh;
            toff[j][hh] = (k < 25) ? (k / 5) * IN_STRIDE + (k % 5) : 39;
        }

    // readback role (fixed per thread)
    const int rch  = tid >> 3;
    const int rpy  = (tid >> 2) & 1;
    const int rpx4 = tid & 3;
    __syncthreads();                      // sbias visible
    const float bch = sbias[rch];

#pragma unroll 1
    for (int it = 0; it < TILES_PER_CTA; it++) {
        int gidx = blockIdx.x * TILES_PER_CTA + it;
        int b  = gidx / IMG_TILES;
        int wt = gidx - b * IMG_TILES;
        int ty = wt / 7, tx = wt - ty * 7;

        // ---- cooperative stage: 8 rows x 40 cols (cols>=36 forced zero)
        {
            const float* xb = x + b * (224 * 224);
            int gr0 = 4 * ty - 2;
            int gc0 = 32 * tx - 2;
#pragma unroll
            for (int idx = tid; idx < 8 * IN_STRIDE; idx += 128) {
                int rr = idx / IN_STRIDE, cc = idx - rr * IN_STRIDE;
                int gr = gr0 + rr, gc = gc0 + cc;
                bool ok = (cc < 36) && ((unsigned)gr < 224u) && ((unsigned)gc < 224u);
                sm_in[idx] = ok ? __ldg(xb + gr * 224 + gc) : 0.0f;
            }
        }
        __syncthreads();

#pragma unroll
        for (int mb = 0; mb < 2; mb++) {
            // this thread's quad coords for block mb
            int pp  = wid * 8 + mb * 4 + q2;     // pooled px in tile
            int pyl = pp >> 4, pxl = pp & 15;
            int base = (2 * pyl) * IN_STRIDE + 2 * pxl + dxg;

            // ---- A fragments straight from staged tile
            // L(dy, j, h) = sm_in[base + dy*IN_STRIDE + toff[j][h]]
#define LTAP(dy, j, hh) sm_in[base + (dy) * IN_STRIDE + toff[j][hh]]
            uint32_t A0 = h2(LTAP(0, 0, 0), LTAP(0, 0, 1));
            uint32_t A1 = h2(LTAP(1, 0, 0), LTAP(1, 0, 1));
            uint32_t A2 = h2(LTAP(0, 1, 0), LTAP(0, 1, 1));
            uint32_t A3 = h2(LTAP(1, 1, 0), LTAP(1, 1, 1));
            uint32_t A4 = h2(LTAP(0, 2, 0), LTAP(0, 2, 1));
            uint32_t A5 = h2(LTAP(1, 2, 0), LTAP(1, 2, 1));
            uint32_t A6 = h2(LTAP(0, 3, 0), LTAP(0, 3, 1));
            uint32_t A7 = h2(LTAP(1, 3, 0), LTAP(1, 3, 1));
#undef LTAP

#pragma unroll
            for (int nb = 0; nb < 2; nb++) {
                float d0 = 0.f, d1 = 0.f, d2 = 0.f, d3 = 0.f;
                mma16816(d0, d1, d2, d3, A0, A1, A2, A3,
                         bfrag[nb][0][0], bfrag[nb][0][1]);
                mma16816(d0, d1, d2, d3, A4, A5, A6, A7,
                         bfrag[nb][1][0], bfrag[nb][1][1]);

                // ---- pool: vertical in-thread, horizontal via shfl.xor(16)
                float vm0 = fmaxf(d0, d2);     // ch = nb*8 + 2*i4
                float vm1 = fmaxf(d1, d3);     // ch + 1
                float o0 = fmaxf(vm0, __shfl_xor_sync(0xFFFFFFFFu, vm0, 16));
                float o1 = fmaxf(vm1, __shfl_xor_sync(0xFFFFFFFFu, vm1, 16));
                if (lane < 16) {               // dx == 0 holders write
                    int ch0  = nb * 8 + 2 * i4;
                    int pidx = pyl * 16 + pxl;
                    sm_pool[ch0 * 36 + pidx]       = o0;
                    sm_pool[(ch0 + 1) * 36 + pidx] = o1;
                }
            }
        }
        __syncthreads();

        // ---- coalesced epilogue: thread -> one float4 (ch, row, 4 px)
        {
            const float* sp = sm_pool + rch * 36 + rpy * 16 + rpx4 * 4;
            float4 v = *reinterpret_cast<const float4*>(sp);
            v.x = fmaxf(v.x + bch, 0.f);
            v.y = fmaxf(v.y + bch, 0.f);
            v.z = fmaxf(v.z + bch, 0.f);
            v.w = fmaxf(v.w + bch, 0.f);
            float* op = out + ((b * 16 + rch) * 112 + (2 * ty + rpy)) * 112
                            + 16 * tx + 4 * rpx4;
            *reinterpret_cast<float4*>(op) = v;
        }
        __syncthreads();   // sm_in/sm_pool reusable next iter
    }
}

extern "C" void kernel_launch(void* const* d_in, const int* in_sizes, int n_in,
                              void* d_out, int out_size) {
    const float* x     = (const float*)d_in[0];
    const float* w     = (const float*)d_in[1];
    const float* bias  = (const float*)d_in[2];
    const float* gamma = (const float*)d_in[3];
    const float* beta  = (const float*)d_in[4];
    const float* mean  = (const float*)d_in[5];
    const float* var   = (const float*)d_in[6];
    float* out = (float*)d_out;

    fuse_params_kernel<<<1, 32>>>(w, bias, gamma, beta, mean, var);
    // 128 images * 392 tiles / 8 tiles per CTA = 6272 CTAs
    conv_hmma_kernel<<<6272, 128>>>(x, out);
}

// round 17
// speedup vs baseline: 2.1574x; 1.1838x over previous
#include <cuda_runtime.h>
#include <cuda_fp16.h>
#include <cstdint>

// ---------------------------------------------------------------------------
// Fused Conv2d(1->16,5x5,pad2) + BN(inference) + ReLU + MaxPool2x2
//   x [128,1,224,224] f32 -> out [128,16,112,112] f32
//
// R16 = R15 resubmitted (R15 bench hit an infra failure: "system not yet
// initialized" from the harness's first CUDA call; kernel never ran).
//
// HMMA implicit GEMM with parity-packed fp16 staging.
//  - K re-layout: tap (i,j) -> slot 6i+j (32 K slots, pads zero-weight) so
//    every mma A-pair (k0,k0+1) is a same-row adjacent pixel pair.
//  - staged tile converted ONCE to two parity-packed half2 arrays;
//    each A fragment register = ONE LDS.32 (was 2 LDS + cvt + pack).
//  - pooling: in-thread vertical max + one shfl.xor(16); smem-transposed
//    coalesced float4 epilogue. (Validated R14 structure.)
// ---------------------------------------------------------------------------

__device__ __half g_wh[16 * 32];   // BN-folded weights fp16, slot layout 6i+j
__device__ float  g_bias[16];      // BN-folded bias fp32

__global__ void fuse_params_kernel(const float* __restrict__ w,
                                   const float* __restrict__ b,
                                   const float* __restrict__ gamma,
                                   const float* __restrict__ beta,
                                   const float* __restrict__ mean,
                                   const float* __restrict__ var) {
    int c = threadIdx.x;
    if (c < 16) {
        float s = gamma[c] * rsqrtf(var[c] + 1e-5f);
        g_bias[c] = b[c] * s + beta[c] - mean[c] * s;
#pragma unroll
        for (int k = 0; k < 32; k++) g_wh[c * 32 + k] = __float2half(0.0f);
#pragma unroll
        for (int i = 0; i < 5; i++)
#pragma unroll
            for (int j = 0; j < 5; j++)
                g_wh[c * 32 + 6 * i + j] = __float2half(w[c * 25 + i * 5 + j] * s);
    }
}

__device__ __forceinline__ void mma16816(float& d0, float& d1, float& d2, float& d3,
                                         uint32_t a0, uint32_t a1, uint32_t a2, uint32_t a3,
                                         uint32_t b0, uint32_t b1) {
    asm volatile(
        "mma.sync.aligned.m16n8k16.row.col.f32.f16.f16.f32 "
        "{%0,%1,%2,%3}, {%4,%5,%6,%7}, {%8,%9}, {%0,%1,%2,%3};"
        : "+f"(d0), "+f"(d1), "+f"(d2), "+f"(d3)
        : "r"(a0), "r"(a1), "r"(a2), "r"(a3), "r"(b0), "r"(b1));
}
__device__ __forceinline__ uint32_t h2(float lo, float hi) {
    __half2 h = __floats2half2_rn(lo, hi);
    return *reinterpret_cast<uint32_t*>(&h);
}

#define TILES_PER_CTA 8
#define IMG_TILES     392   // 56 * 7
#define FSTRIDE       42    // f32 staged tile stride (36 valid + zeros)
#define ROWST         20    // parity array: half2 per row
#define PARST         168   // parity block stride (== 8 mod 32 -> bank split)

__global__ __launch_bounds__(128, 6)
void conv_hmma_kernel(const float* __restrict__ x, float* __restrict__ out) {
    __shared__ float   sm_f[8 * FSTRIDE];     // staged f32 tile (halo, padded)
    __shared__ __half2 sm_pk[2 * PARST];      // parity-packed fp16 pairs
    __shared__ float   sm_pool[16 * 36];      // pooled [ch]: 2x16 px, stride 36
    __shared__ float   sbias[16];

    const int tid  = threadIdx.x;
    const int wid  = tid >> 5;
    const int lane = tid & 31;
    const int i4   = lane & 3;        // K-pair group
    const int g4   = lane >> 2;       // row group 0..7
    const int dxg  = g4 >> 2;         // dx of this thread's rows (= lane bit 4)
    const int q2   = g4 & 3;

    if (tid < 16) sbias[tid] = g_bias[tid];

    // ---- B fragments (weights) in slot layout: same index math as R13/R14.
    uint32_t bfrag[2][2][2];
#pragma unroll
    for (int nb = 0; nb < 2; nb++)
#pragma unroll
        for (int kc = 0; kc < 2; kc++) {
            int n  = nb * 8 + g4;
            int k0 = kc * 16 + i4 * 2;
            bfrag[nb][kc][0] = h2(__half2float(g_wh[n * 32 + k0]),
                                  __half2float(g_wh[n * 32 + k0 + 1]));
            bfrag[nb][kc][1] = h2(__half2float(g_wh[n * 32 + k0 + 8]),
                                  __half2float(g_wh[n * 32 + k0 + 9]));
        }

    // ---- per-thread A offsets: k0 = 2*i4 + 8*j -> slot (i',j') = (k0/6, k0%6)
    // off = i'*ROWST + j'/2 (in half2 units). k0=30 (i'=5) is zero-weight ->
    // clamp to 0 to stay in-bounds (value irrelevant).
    int aoff[4];
#pragma unroll
    for (int j = 0; j < 4; j++) {
        int k0 = 2 * i4 + 8 * j;
        aoff[j] = (k0 >= 30) ? 0 : (k0 / 6) * ROWST + (k0 % 6) / 2;
    }

    // readback role (fixed per thread)
    const int rch  = tid >> 3;
    const int rpy  = (tid >> 2) & 1;
    const int rpx4 = tid & 3;
    __syncthreads();
    const float bch = sbias[rch];

#pragma unroll 1
    for (int it = 0; it < TILES_PER_CTA; it++) {
        int gidx = blockIdx.x * TILES_PER_CTA + it;
        int b  = gidx / IMG_TILES;
        int wt = gidx - b * IMG_TILES;
        int ty = wt / 7, tx = wt - ty * 7;

        // ---- pass 1: stage f32 tile 8 x 42 (cols >=36 zero, halo zero-padded)
        {
            const float* xb = x + b * (224 * 224);
            int gr0 = 4 * ty - 2;
            int gc0 = 32 * tx - 2;
#pragma unroll
            for (int idx = tid; idx < 8 * FSTRIDE; idx += 128) {
                int rr = idx / FSTRIDE, cc = idx - rr * FSTRIDE;
                int gr = gr0 + rr, gc = gc0 + cc;
                bool ok = (cc < 36) && ((unsigned)gr < 224u) && ((unsigned)gc < 224u);
                sm_f[idx] = ok ? __ldg(xb + gr * 224 + gc) : 0.0f;
            }
        }
        __syncthreads();

        // ---- pass 2: build parity-packed half2 arrays (320 entries)
        {
#pragma unroll
            for (int e = tid; e < 320; e += 128) {
                int p   = e / 160;
                int rem = e - p * 160;
                int row = rem / ROWST;
                int cp  = rem - row * ROWST;
                int col = 2 * cp + p;
                const float* f = sm_f + row * FSTRIDE + col;
                sm_pk[p * PARST + row * ROWST + cp] =
                    __floats2half2_rn(f[0], f[1]);
            }
        }
        __syncthreads();

#pragma unroll
        for (int mb = 0; mb < 2; mb++) {
            int pp  = wid * 8 + mb * 4 + q2;     // pooled px in tile
            int pyl = pp >> 4, pxl = pp & 15;
            // base (half2 units): parity dxg, window row 2*pyl, col-pair pxl
            const __half2* pb = sm_pk + dxg * PARST + (2 * pyl) * ROWST + pxl;

#define LPAIR(dy, j) (*reinterpret_cast<const uint32_t*>(pb + (dy) * ROWST + aoff[j]))
            uint32_t A0 = LPAIR(0, 0);
            uint32_t A1 = LPAIR(1, 0);
            uint32_t A2 = LPAIR(0, 1);
            uint32_t A3 = LPAIR(1, 1);
            uint32_t A4 = LPAIR(0, 2);
            uint32_t A5 = LPAIR(1, 2);
            uint32_t A6 = LPAIR(0, 3);
            uint32_t A7 = LPAIR(1, 3);
#undef LPAIR

#pragma unroll
            for (int nb = 0; nb < 2; nb++) {
                float d0 = 0.f, d1 = 0.f, d2 = 0.f, d3 = 0.f;
                mma16816(d0, d1, d2, d3, A0, A1, A2, A3,
                         bfrag[nb][0][0], bfrag[nb][0][1]);
                mma16816(d0, d1, d2, d3, A4, A5, A6, A7,
                         bfrag[nb][1][0], bfrag[nb][1][1]);

                // pool: vertical in-thread, horizontal via shfl.xor(16)
                float vm0 = fmaxf(d0, d2);     // ch = nb*8 + 2*i4
                float vm1 = fmaxf(d1, d3);     // ch + 1
                float o0 = fmaxf(vm0, __shfl_xor_sync(0xFFFFFFFFu, vm0, 16));
                float o1 = fmaxf(vm1, __shfl_xor_sync(0xFFFFFFFFu, vm1, 16));
                if (lane < 16) {               // dx == 0 holders write
                    int ch0  = nb * 8 + 2 * i4;
                    int pidx = pyl * 16 + pxl;
                    sm_pool[ch0 * 36 + pidx]       = o0;
                    sm_pool[(ch0 + 1) * 36 + pidx] = o1;
                }
            }
        }
        __syncthreads();

        // ---- coalesced epilogue: thread -> one float4 (ch, row, 4 px)
        {
            const float* sp = sm_pool + rch * 36 + rpy * 16 + rpx4 * 4;
            float4 v = *reinterpret_cast<const float4*>(sp);
            v.x = fmaxf(v.x + bch, 0.f);
            v.y = fmaxf(v.y + bch, 0.f);
            v.z = fmaxf(v.z + bch, 0.f);
            v.w = fmaxf(v.w + bch, 0.f);
            float* op = out + ((b * 16 + rch) * 112 + (2 * ty + rpy)) * 112
                            + 16 * tx + 4 * rpx4;
            *reinterpret_cast<float4*>(op) = v;
        }
        __syncthreads();   // smem reusable next iter
    }
}

extern "C" void kernel_launch(void* const* d_in, const int* in_sizes, int n_in,
                              void* d_out, int out_size) {
    const float* x     = (const float*)d_in[0];
    const float* w     = (const float*)d_in[1];
    const float* bias  = (const float*)d_in[2];
    const float* gamma = (const float*)d_in[3];
    const float* beta  = (const float*)d_in[4];
    const float* mean  = (const float*)d_in[5];
    const float* var   = (const float*)d_in[6];
    float* out = (float*)d_out;

    fuse_params_kernel<<<1, 32>>>(w, bias, gamma, beta, mean, var);
    // 128 images * 392 tiles / 8 tiles per CTA = 6272 CTAs
    conv_hmma_kernel<<<6272, 128>>>(x, out);
}